// round 1
// baseline (speedup 1.0000x reference)
#include <cuda_runtime.h>

// Problem constants
#define HW     900
#define IMG_H  30
#define IMG_W  30
#define NBATCH 2
#define NHEAD  8
#define WS2    225
#define INVT   0.17677669529663687f   // 1/sqrt(32)

#define RB     3                       // rows per attention band
#define SROWS  (RB + 14)               // 17 smem rows
#define SPIX   (SROWS * IMG_W)         // 510 smem pixels per tile

// ---------------- scratch (device globals: no allocation allowed) ----------
__device__ float g_qkf   [NBATCH * 256 * HW];
__device__ float g_vvp   [NBATCH * 256 * HW];
__device__ float g_uup   [NBATCH * 256 * HW];
__device__ float g_rel   [NBATCH * NHEAD * WS2 * HW];
__device__ float g_gated [NBATCH * 256 * HW];
__device__ float g_dw    [NBATCH * 256 * HW];
__device__ float g_attn_fb[NBATCH * NHEAD * WS2 * HW];

// ---------------- qk_feat = Wqk @ q + bqk  (M=256,K=256,P=900, batch 2) ----
__global__ void k_qkf(const float* __restrict__ q, const float* __restrict__ Wqk,
                      const float* __restrict__ bqk) {
    __shared__ float Ws[32][64];
    __shared__ float Xs[32][64];
    int n  = blockIdx.z;
    int o0 = blockIdx.y * 64, p0 = blockIdx.x * 64;
    const float* X = q + n * 256 * HW;
    float acc[4][4];
#pragma unroll
    for (int i = 0; i < 4; i++)
#pragma unroll
        for (int j = 0; j < 4; j++) acc[i][j] = 0.f;
    int tx = threadIdx.x & 15, ty = threadIdx.x >> 4;
    for (int c0 = 0; c0 < 256; c0 += 32) {
        for (int i = threadIdx.x; i < 2048; i += 256) {
            int c = i & 31, o = i >> 5;
            Ws[c][o] = Wqk[(o0 + o) * 256 + c0 + c];
        }
        for (int i = threadIdx.x; i < 2048; i += 256) {
            int p = i & 63, c = i >> 6;
            int pp = p0 + p;
            Xs[c][p] = (pp < HW) ? X[(c0 + c) * HW + pp] : 0.f;
        }
        __syncthreads();
#pragma unroll
        for (int c = 0; c < 32; c++) {
            float4 a4 = *reinterpret_cast<const float4*>(&Ws[c][ty * 4]);
            float4 b4 = *reinterpret_cast<const float4*>(&Xs[c][tx * 4]);
            float a[4] = {a4.x, a4.y, a4.z, a4.w};
            float b[4] = {b4.x, b4.y, b4.z, b4.w};
#pragma unroll
            for (int i = 0; i < 4; i++)
#pragma unroll
                for (int j = 0; j < 4; j++) acc[i][j] += a[i] * b[j];
        }
        __syncthreads();
    }
#pragma unroll
    for (int i = 0; i < 4; i++) {
        int o = o0 + ty * 4 + i;
        float bb = bqk[o];
#pragma unroll
        for (int j = 0; j < 4; j++) {
            int p = p0 + tx * 4 + j;
            if (p < HW) g_qkf[(n * 256 + o) * HW + p] = acc[i][j] + bb;
        }
    }
}

// ---------------- grouped 1x1 conv + SiLU + head interleave (v and u) ------
// grid.z: n*4 + which*2 + g   (which: 0=v, 1=u; g: group)
__global__ void k_vu(const float* __restrict__ v, const float* __restrict__ u,
                     const float* __restrict__ Wv, const float* __restrict__ bv,
                     const float* __restrict__ Wu, const float* __restrict__ bu) {
    __shared__ float Ws[32][64];
    __shared__ float Xs[32][64];
    int z = blockIdx.z;
    int n = z >> 2, which = (z >> 1) & 1, g = z & 1;
    const float* src  = (which ? u  : v ) + (n * 256 + g * 128) * HW;
    const float* W    = (which ? Wu : Wv) + g * 128 * 128;
    const float* bias = (which ? bu : bv) + g * 128;
    float* dst = which ? g_uup : g_vvp;
    int o0 = blockIdx.y * 64, p0 = blockIdx.x * 64;
    float acc[4][4];
#pragma unroll
    for (int i = 0; i < 4; i++)
#pragma unroll
        for (int j = 0; j < 4; j++) acc[i][j] = 0.f;
    int tx = threadIdx.x & 15, ty = threadIdx.x >> 4;
    for (int c0 = 0; c0 < 128; c0 += 32) {
        for (int i = threadIdx.x; i < 2048; i += 256) {
            int c = i & 31, o = i >> 5;
            Ws[c][o] = W[(o0 + o) * 128 + c0 + c];
        }
        for (int i = threadIdx.x; i < 2048; i += 256) {
            int p = i & 63, c = i >> 6;
            int pp = p0 + p;
            Xs[c][p] = (pp < HW) ? src[(c0 + c) * HW + pp] : 0.f;
        }
        __syncthreads();
#pragma unroll
        for (int c = 0; c < 32; c++) {
            float4 a4 = *reinterpret_cast<const float4*>(&Ws[c][ty * 4]);
            float4 b4 = *reinterpret_cast<const float4*>(&Xs[c][tx * 4]);
            float a[4] = {a4.x, a4.y, a4.z, a4.w};
            float b[4] = {b4.x, b4.y, b4.z, b4.w};
#pragma unroll
            for (int i = 0; i < 4; i++)
#pragma unroll
                for (int j = 0; j < 4; j++) acc[i][j] += a[i] * b[j];
        }
        __syncthreads();
    }
#pragma unroll
    for (int i = 0; i < 4; i++) {
        int o = o0 + ty * 4 + i;
        float bb = bias[o];
        int head = o >> 4, c16 = o & 15;
        int d = head * 32 + g * 16 + c16;      // interleaved head-major channel
#pragma unroll
        for (int j = 0; j < 4; j++) {
            int p = p0 + tx * 4 + j;
            if (p < HW) {
                float val = acc[i][j] + bb;
                val = val / (1.f + __expf(-val));   // SiLU
                dst[(n * 256 + d) * HW + p] = val;
            }
        }
    }
}

// ---------------- rel = Wrel[head] @ qh + brel  (M=225,K=32, 16 batches) ---
__global__ void k_rel(const float* __restrict__ Wrel, const float* __restrict__ brel) {
    __shared__ float Wsm[WS2 * 32];
    __shared__ float bsm[WS2];
    __shared__ float Xs[32][60];
    int nh = blockIdx.y;
    int n = nh >> 3, head = nh & 7;
    int p0 = blockIdx.x * 60;
    for (int i = threadIdx.x; i < WS2 * 32; i += 256) Wsm[i] = Wrel[head * WS2 * 32 + i];
    for (int i = threadIdx.x; i < WS2; i += 256)      bsm[i] = brel[head * WS2 + i];
    for (int i = threadIdx.x; i < 32 * 60; i += 256) {
        int c = i / 60, p = i % 60;
        Xs[c][p] = g_qkf[(n * 256 + head * 32 + c) * HW + p0 + p];
    }
    __syncthreads();
    if (threadIdx.x >= 240) return;
    int px = threadIdx.x % 60, ol = threadIdx.x / 60;
    float xr[32];
#pragma unroll
    for (int c = 0; c < 32; c++) xr[c] = Xs[c][px];
    float* out = g_rel + (nh * WS2) * HW + p0 + px;
    for (int o = ol; o < WS2; o += 4) {
        const float* w = &Wsm[o * 32];
        float s0 = 0.f, s1 = 0.f, s2 = 0.f, s3 = 0.f;
#pragma unroll
        for (int c = 0; c < 32; c += 4) {
            s0 += w[c    ] * xr[c    ];
            s1 += w[c + 1] * xr[c + 1];
            s2 += w[c + 2] * xr[c + 2];
            s3 += w[c + 3] * xr[c + 3];
        }
        out[o * HW] = (s0 + s1) + (s2 + s3) + bsm[o];
    }
}

// ---------------- fused windowed attention: scores+softmax+agg+gate --------
// grid: (10 bands, 8 heads, 2 batch), block 96 (lane = pixel), dyn smem 2*32*510*4
__global__ void k_attn(float* __restrict__ attn_ext, int use_ext) {
    extern __shared__ float sm[];
    float* k_sm = sm;
    float* v_sm = sm + 32 * SPIX;
    int band = blockIdx.x, head = blockIdx.y, n = blockIdx.z;
    int y0 = band * RB;
    int ystart = y0 - 7;
    const float* qf = g_qkf + (n * 256 + head * 32) * HW;
    const float* vv = g_vvp + (n * 256 + head * 32) * HW;
    for (int i = threadIdx.x; i < 32 * SPIX; i += blockDim.x) {
        int c = i / SPIX, idx = i - c * SPIX;
        int gy = ystart + idx / IMG_W;
        float kv = 0.f, vvv = 0.f;
        if (gy >= 0 && gy < IMG_H) {
            int gp = gy * IMG_W + (idx % IMG_W);
            kv  = qf[c * HW + gp];
            vvv = vv[c * HW + gp];
        }
        k_sm[c * SPIX + idx] = kv;
        v_sm[c * SPIX + idx] = vvv;
    }
    __syncthreads();
    int t = threadIdx.x;
    if (t >= RB * IMG_W) return;
    int p = y0 * IMG_W + t;
    int y = p / IMG_W, x = p - y * IMG_W;
    int lidx = t + 7 * IMG_W;          // smem index of own pixel
    float qs[32];
#pragma unroll
    for (int c = 0; c < 32; c++) qs[c] = k_sm[c * SPIX + lidx] * INVT;

    float* attn_p = (use_ext ? attn_ext : g_attn_fb) + ((n * NHEAD + head) * WS2) * HW + p;
    const float* rel_p = g_rel + ((n * NHEAD + head) * WS2) * HW + p;

    float m = -1e30f, l = 0.f;
    // pass 1: raw scores + online softmax stats; stage raw scores in attn buf
    for (int oy = 0; oy < 15; oy++) {
        int ny = y + oy - 7;
        bool yok = (ny >= 0) && (ny < IMG_H);
        int rowbase = (ny - ystart) * IMG_W;
        for (int ox = 0; ox < 15; ox++) {
            int o = oy * 15 + ox;
            int nx = x + ox - 7;
            float s;
            if (yok && nx >= 0 && nx < IMG_W) {
                int idx = rowbase + nx;
                float s0 = 0.f, s1 = 0.f, s2 = 0.f, s3 = 0.f;
#pragma unroll
                for (int c = 0; c < 32; c += 4) {
                    s0 += qs[c    ] * k_sm[(c    ) * SPIX + idx];
                    s1 += qs[c + 1] * k_sm[(c + 1) * SPIX + idx];
                    s2 += qs[c + 2] * k_sm[(c + 2) * SPIX + idx];
                    s3 += qs[c + 3] * k_sm[(c + 3) * SPIX + idx];
                }
                s = (s0 + s1) + (s2 + s3) + rel_p[o * HW];
            } else {
                s = -1e8f;
            }
            attn_p[o * HW] = s;
            if (s > m) { l = l * __expf(m - s) + 1.f; m = s; }
            else       { l += __expf(s - m); }
        }
    }
    float inv_l = 1.f / l;
    float agg[32];
#pragma unroll
    for (int c = 0; c < 32; c++) agg[c] = 0.f;
    // pass 2: normalize + aggregate
    for (int oy = 0; oy < 15; oy++) {
        int ny = y + oy - 7;
        bool yok = (ny >= 0) && (ny < IMG_H);
        int rowbase = (ny - ystart) * IMG_W;
        for (int ox = 0; ox < 15; ox++) {
            int o = oy * 15 + ox;
            int nx = x + ox - 7;
            float s = attn_p[o * HW];
            float a = __expf(s - m) * inv_l;
            attn_p[o * HW] = a;
            if (yok && nx >= 0 && nx < IMG_W) {
                int idx = rowbase + nx;
#pragma unroll
                for (int c = 0; c < 32; c++) agg[c] += a * v_sm[c * SPIX + idx];
            }
        }
    }
    const float* uu = g_uup + (n * 256 + head * 32) * HW;
    float* gd = g_gated + (n * 256 + head * 32) * HW;
#pragma unroll
    for (int c = 0; c < 32; c++) gd[c * HW + p] = agg[c] * uu[c * HW + p];
}

// ---------------- depthwise 5x5 conv (pad 2, no bias) ----------------------
__global__ void k_dw(const float* __restrict__ Wdw) {
    int i = blockIdx.x * blockDim.x + threadIdx.x;
    if (i >= NBATCH * 256 * HW) return;
    int p = i % HW;
    int d = (i / HW) & 255;
    int n = i / (HW * 256);
    int y = p / IMG_W, x = p - y * IMG_W;
    const float* src = g_gated + (n * 256 + d) * HW;
    const float* w = Wdw + d * 25;
    float sum = 0.f;
#pragma unroll
    for (int ky = 0; ky < 5; ky++) {
        int ny = y + ky - 2;
        if (ny < 0 || ny >= IMG_H) continue;
#pragma unroll
        for (int kx = 0; kx < 5; kx++) {
            int nx = x + kx - 2;
            if (nx < 0 || nx >= IMG_W) continue;
            sum += w[ky * 5 + kx] * src[ny * IMG_W + nx];
        }
    }
    g_dw[(n * 256 + d) * HW + p] = sum;
}

// ---------------- final projection (M=128,K=256) ---------------------------
__global__ void k_proj(const float* __restrict__ Wproj, const float* __restrict__ bproj,
                       float* __restrict__ out) {
    __shared__ float Ws[32][64];
    __shared__ float Xs[32][64];
    int n = blockIdx.z;
    int o0 = blockIdx.y * 64, p0 = blockIdx.x * 64;
    const float* X = g_dw + n * 256 * HW;
    float acc[4][4];
#pragma unroll
    for (int i = 0; i < 4; i++)
#pragma unroll
        for (int j = 0; j < 4; j++) acc[i][j] = 0.f;
    int tx = threadIdx.x & 15, ty = threadIdx.x >> 4;
    for (int c0 = 0; c0 < 256; c0 += 32) {
        for (int i = threadIdx.x; i < 2048; i += 256) {
            int c = i & 31, o = i >> 5;
            Ws[c][o] = Wproj[(o0 + o) * 256 + c0 + c];
        }
        for (int i = threadIdx.x; i < 2048; i += 256) {
            int p = i & 63, c = i >> 6;
            int pp = p0 + p;
            Xs[c][p] = (pp < HW) ? X[(c0 + c) * HW + pp] : 0.f;
        }
        __syncthreads();
#pragma unroll
        for (int c = 0; c < 32; c++) {
            float4 a4 = *reinterpret_cast<const float4*>(&Ws[c][ty * 4]);
            float4 b4 = *reinterpret_cast<const float4*>(&Xs[c][tx * 4]);
            float a[4] = {a4.x, a4.y, a4.z, a4.w};
            float b[4] = {b4.x, b4.y, b4.z, b4.w};
#pragma unroll
            for (int i = 0; i < 4; i++)
#pragma unroll
                for (int j = 0; j < 4; j++) acc[i][j] += a[i] * b[j];
        }
        __syncthreads();
    }
#pragma unroll
    for (int i = 0; i < 4; i++) {
        int o = o0 + ty * 4 + i;
        float bb = bproj[o];
#pragma unroll
        for (int j = 0; j < 4; j++) {
            int p = p0 + tx * 4 + j;
            if (p < HW) out[p * (NBATCH * 128) + n * 128 + o] = acc[i][j] + bb;
        }
    }
}

// ---------------------------------------------------------------------------
extern "C" void kernel_launch(void* const* d_in, const int* in_sizes, int n_in,
                              void* d_out, int out_size) {
    const float* q     = (const float*)d_in[0];
    // d_in[1] = k : unused (overwritten by linear_QK(q) in the reference)
    const float* v     = (const float*)d_in[2];
    const float* u     = (const float*)d_in[3];
    const float* Wqk   = (const float*)d_in[4];
    const float* bqk   = (const float*)d_in[5];
    const float* Wv    = (const float*)d_in[6];
    const float* bv    = (const float*)d_in[7];
    const float* Wu    = (const float*)d_in[8];
    const float* bu    = (const float*)d_in[9];
    const float* Wrel  = (const float*)d_in[10];
    const float* brel  = (const float*)d_in[11];
    const float* Wdw   = (const float*)d_in[12];
    const float* Wproj = (const float*)d_in[13];
    const float* bproj = (const float*)d_in[14];
    float* out = (float*)d_out;

    const int OUT0 = HW * NBATCH * 128;                 // 230400
    const int OUT1 = NBATCH * NHEAD * WS2 * HW;         // 3240000
    int use_ext = (out_size >= OUT0 + OUT1) ? 1 : 0;
    float* attn_ext = out + OUT0;

    const int attn_smem = 2 * 32 * SPIX * (int)sizeof(float);  // 130560
    cudaFuncSetAttribute(k_attn, cudaFuncAttributeMaxDynamicSharedMemorySize, attn_smem);

    k_qkf <<<dim3(15, 4, 2), 256>>>(q, Wqk, bqk);
    k_vu  <<<dim3(15, 2, 8), 256>>>(v, u, Wv, bv, Wu, bu);
    k_rel <<<dim3(15, 16),   256>>>(Wrel, brel);
    k_attn<<<dim3(10, 8, 2), 96, attn_smem>>>(attn_ext, use_ext);
    k_dw  <<<dim3((NBATCH * 256 * HW + 255) / 256), 256>>>(Wdw);
    k_proj<<<dim3(15, 2, 2), 256>>>(Wproj, bproj, out);
}

// round 2
// speedup vs baseline: 2.3113x; 2.3113x over previous
#include <cuda_runtime.h>

// Problem constants
#define HW     900
#define IMG_H  30
#define IMG_W  30
#define NBATCH 2
#define NHEAD  8
#define WS2    225
#define INVT   0.17677669529663687f   // 1/sqrt(32)

#define TROW   32                      // padded tile row stride (bank-friendly)
#define TPIX   (15 * TROW)             // 480 smem pixels per channel

// ---------------- scratch (device globals: no allocation allowed) ----------
__device__ float g_qkf   [NBATCH * 256 * HW];            // [n][c][p]
__device__ float g_vvp   [NBATCH * 256 * HW];            // [n][c][p]
__device__ float g_uup   [NBATCH * HW * 256];            // [n][p][c]
__device__ float g_rel   [NBATCH * NHEAD * HW * WS2];    // [nh][p][o]
__device__ float g_gated [NBATCH * HW * 256];            // [n][p][c]
__device__ float g_dw    [NBATCH * 256 * HW];            // [n][c][p]
__device__ float g_attn_fb[NBATCH * NHEAD * WS2 * HW];

// ---------------- qk_feat = Wqk @ q + bqk  (M=256,K=256,P=900, batch 2) ----
__global__ void k_qkf(const float* __restrict__ q, const float* __restrict__ Wqk,
                      const float* __restrict__ bqk) {
    __shared__ float Ws[32][64];
    __shared__ float Xs[32][64];
    int n  = blockIdx.z;
    int o0 = blockIdx.y * 64, p0 = blockIdx.x * 64;
    const float* X = q + n * 256 * HW;
    float acc[4][4];
#pragma unroll
    for (int i = 0; i < 4; i++)
#pragma unroll
        for (int j = 0; j < 4; j++) acc[i][j] = 0.f;
    int tx = threadIdx.x & 15, ty = threadIdx.x >> 4;
    for (int c0 = 0; c0 < 256; c0 += 32) {
        for (int i = threadIdx.x; i < 2048; i += 256) {
            int c = i & 31, o = i >> 5;
            Ws[c][o] = Wqk[(o0 + o) * 256 + c0 + c];
        }
        for (int i = threadIdx.x; i < 2048; i += 256) {
            int p = i & 63, c = i >> 6;
            int pp = p0 + p;
            Xs[c][p] = (pp < HW) ? X[(c0 + c) * HW + pp] : 0.f;
        }
        __syncthreads();
#pragma unroll
        for (int c = 0; c < 32; c++) {
            float4 a4 = *reinterpret_cast<const float4*>(&Ws[c][ty * 4]);
            float4 b4 = *reinterpret_cast<const float4*>(&Xs[c][tx * 4]);
            float a[4] = {a4.x, a4.y, a4.z, a4.w};
            float b[4] = {b4.x, b4.y, b4.z, b4.w};
#pragma unroll
            for (int i = 0; i < 4; i++)
#pragma unroll
                for (int j = 0; j < 4; j++) acc[i][j] += a[i] * b[j];
        }
        __syncthreads();
    }
#pragma unroll
    for (int i = 0; i < 4; i++) {
        int o = o0 + ty * 4 + i;
        float bb = bqk[o];
#pragma unroll
        for (int j = 0; j < 4; j++) {
            int p = p0 + tx * 4 + j;
            if (p < HW) g_qkf[(n * 256 + o) * HW + p] = acc[i][j] + bb;
        }
    }
}

// ---------------- grouped 1x1 conv + SiLU + head interleave (v and u) ------
// grid.z: n*4 + which*2 + g   (which: 0=v, 1=u; g: group)
__global__ void k_vu(const float* __restrict__ v, const float* __restrict__ u,
                     const float* __restrict__ Wv, const float* __restrict__ bv,
                     const float* __restrict__ Wu, const float* __restrict__ bu) {
    __shared__ float Ws[32][64];
    __shared__ float Xs[32][64];
    int z = blockIdx.z;
    int n = z >> 2, which = (z >> 1) & 1, g = z & 1;
    const float* src  = (which ? u  : v ) + (n * 256 + g * 128) * HW;
    const float* W    = (which ? Wu : Wv) + g * 128 * 128;
    const float* bias = (which ? bu : bv) + g * 128;
    int o0 = blockIdx.y * 64, p0 = blockIdx.x * 64;
    float acc[4][4];
#pragma unroll
    for (int i = 0; i < 4; i++)
#pragma unroll
        for (int j = 0; j < 4; j++) acc[i][j] = 0.f;
    int tx = threadIdx.x & 15, ty = threadIdx.x >> 4;
    for (int c0 = 0; c0 < 128; c0 += 32) {
        for (int i = threadIdx.x; i < 2048; i += 256) {
            int c = i & 31, o = i >> 5;
            Ws[c][o] = W[(o0 + o) * 128 + c0 + c];
        }
        for (int i = threadIdx.x; i < 2048; i += 256) {
            int p = i & 63, c = i >> 6;
            int pp = p0 + p;
            Xs[c][p] = (pp < HW) ? src[(c0 + c) * HW + pp] : 0.f;
        }
        __syncthreads();
#pragma unroll
        for (int c = 0; c < 32; c++) {
            float4 a4 = *reinterpret_cast<const float4*>(&Ws[c][ty * 4]);
            float4 b4 = *reinterpret_cast<const float4*>(&Xs[c][tx * 4]);
            float a[4] = {a4.x, a4.y, a4.z, a4.w};
            float b[4] = {b4.x, b4.y, b4.z, b4.w};
#pragma unroll
            for (int i = 0; i < 4; i++)
#pragma unroll
                for (int j = 0; j < 4; j++) acc[i][j] += a[i] * b[j];
        }
        __syncthreads();
    }
#pragma unroll
    for (int i = 0; i < 4; i++) {
        int o = o0 + ty * 4 + i;
        float bb = bias[o];
        int head = o >> 4, c16 = o & 15;
        int d = head * 32 + g * 16 + c16;      // interleaved head-major channel
#pragma unroll
        for (int j = 0; j < 4; j++) {
            int p = p0 + tx * 4 + j;
            if (p < HW) {
                float val = acc[i][j] + bb;
                val = val / (1.f + __expf(-val));   // SiLU
                if (which) g_uup[(n * HW + p) * 256 + d] = val;   // [n][p][c]
                else       g_vvp[(n * 256 + d) * HW + p] = val;   // [n][c][p]
            }
        }
    }
}

// ---------------- rel = Wrel[head] @ qh + brel -> [nh][p][o] layout --------
// grid (15 p-tiles of 60, 16 nh), block 256 (thread = o)
__global__ void k_rel(const float* __restrict__ Wrel, const float* __restrict__ brel) {
    extern __shared__ float rsm[];
    float* Xs  = rsm;           // [32][60]
    float* Ssm = rsm + 32 * 60; // [60][225]
    int nh = blockIdx.y;
    int n = nh >> 3, head = nh & 7;
    int p0 = blockIdx.x * 60;
    int tid = threadIdx.x;
    for (int i = tid; i < 32 * 60; i += 256) {
        int c = i / 60, px = i - c * 60;
        Xs[c * 60 + px] = g_qkf[(n * 256 + head * 32 + c) * HW + p0 + px];
    }
    __syncthreads();
    int o = tid;
    if (o < WS2) {
        float w[32];
#pragma unroll
        for (int c = 0; c < 32; c++) w[c] = Wrel[(head * WS2 + o) * 32 + c];
        float bb = brel[head * WS2 + o];
        for (int pq = 0; pq < 15; pq++) {
            float4 acc = {bb, bb, bb, bb};
#pragma unroll
            for (int c = 0; c < 32; c++) {
                float4 xq = *reinterpret_cast<const float4*>(&Xs[c * 60 + pq * 4]);
                acc.x += w[c] * xq.x; acc.y += w[c] * xq.y;
                acc.z += w[c] * xq.z; acc.w += w[c] * xq.w;
            }
            Ssm[(pq * 4 + 0) * WS2 + o] = acc.x;
            Ssm[(pq * 4 + 1) * WS2 + o] = acc.y;
            Ssm[(pq * 4 + 2) * WS2 + o] = acc.z;
            Ssm[(pq * 4 + 3) * WS2 + o] = acc.w;
        }
    }
    __syncthreads();
    float* dst = g_rel + (size_t)(nh * HW + p0) * WS2;
    for (int i = tid; i < 60 * WS2; i += 256) dst[i] = Ssm[i];
}

// ---------------- fused windowed attention: warp-per-pixel ------------------
// grid (30 rows, 8 heads, 2 batch), block 960 (warp = pixel), dyn smem 150KB
__global__ void __launch_bounds__(960, 1) k_attn(float* __restrict__ attn_out) {
    extern __shared__ float sm[];
    float* k_sm  = sm;                 // 32 * 480
    float* v_sm  = sm + 32 * TPIX;     // 32 * 480
    float* a_buf = sm + 64 * TPIX;     // 30 * 225
    int y0 = blockIdx.x, head = blockIdx.y, n = blockIdx.z;
    int nh = n * NHEAD + head;
    const float* qf = g_qkf + (n * 256 + head * 32) * HW;
    const float* vv = g_vvp + (n * 256 + head * 32) * HW;
    int tid = threadIdx.x;

    // load k and v tiles (rows y0-7..y0+7, padded row stride 32, zeros outside)
    for (int i = tid; i < 32 * TPIX; i += 960) {
        int c = i / TPIX, idx = i - c * TPIX;
        int ty = idx >> 5, nx = idx & 31;
        int gy = y0 - 7 + ty;
        float kv = 0.f, vvv = 0.f;
        if (gy >= 0 && gy < IMG_H && nx < IMG_W) {
            int gp = gy * IMG_W + nx;
            kv  = qf[c * HW + gp];
            vvv = vv[c * HW + gp];
        }
        k_sm[i] = kv;
        v_sm[i] = vvv;
    }
    __syncthreads();

    int w    = tid >> 5;   // warp = pixel x
    int lane = tid & 31;
    int x = w;
    int p = y0 * IMG_W + x;

    // q vector (broadcast reads: whole warp same address)
    float qs[32];
#pragma unroll
    for (int c = 0; c < 32; c++) qs[c] = k_sm[c * TPIX + 7 * TROW + x] * INVT;

    const float* rel_p = g_rel + (size_t)(nh * HW + p) * WS2;

    // scores: 8 positions per lane
    float sv[8];
    float m = -1e30f;
#pragma unroll
    for (int i = 0; i < 8; i++) {
        int o = i * 32 + lane;
        float s = -1e30f;
        if (o < WS2) {
            int oy = o / 15, ox = o - oy * 15;
            int ny = y0 + oy - 7;
            int nx = x + ox - 7;
            if (ny >= 0 && ny < IMG_H && nx >= 0 && nx < IMG_W) {
                int idx = oy * TROW + nx;
                float s0 = 0.f, s1 = 0.f, s2 = 0.f, s3 = 0.f;
#pragma unroll
                for (int c = 0; c < 32; c += 4) {
                    s0 += qs[c    ] * k_sm[(c    ) * TPIX + idx];
                    s1 += qs[c + 1] * k_sm[(c + 1) * TPIX + idx];
                    s2 += qs[c + 2] * k_sm[(c + 2) * TPIX + idx];
                    s3 += qs[c + 3] * k_sm[(c + 3) * TPIX + idx];
                }
                s = (s0 + s1) + (s2 + s3) + rel_p[o];
            } else {
                s = -1e8f;   // masked: exp underflows to exactly 0, as in reference
            }
        }
        sv[i] = s;
        m = fmaxf(m, s);
    }
    // warp softmax
#pragma unroll
    for (int sh = 16; sh; sh >>= 1) m = fmaxf(m, __shfl_xor_sync(0xffffffffu, m, sh));
    float l = 0.f;
    float av[8];
#pragma unroll
    for (int i = 0; i < 8; i++) { av[i] = __expf(sv[i] - m); l += av[i]; }
#pragma unroll
    for (int sh = 16; sh; sh >>= 1) l += __shfl_xor_sync(0xffffffffu, l, sh);
    float inv_l = 1.f / l;
#pragma unroll
    for (int i = 0; i < 8; i++) {
        av[i] *= inv_l;
        int o = i * 32 + lane;
        if (o < WS2) a_buf[x * WS2 + o] = av[i];
    }

    // aggregation: per-lane partials over its positions
    float agg[32];
#pragma unroll
    for (int c = 0; c < 32; c++) agg[c] = 0.f;
    for (int i = 0; i < 8; i++) {
        int o = i * 32 + lane;
        if (o < WS2) {
            int oy = o / 15, ox = o - oy * 15;
            int ny = y0 + oy - 7;
            int nx = x + ox - 7;
            if (ny >= 0 && ny < IMG_H && nx >= 0 && nx < IMG_W) {
                int idx = oy * TROW + nx;
                float a = av[i];
#pragma unroll
                for (int c = 0; c < 32; c++) agg[c] += a * v_sm[c * TPIX + idx];
            }
        }
    }
    // butterfly reduce-scatter: lane c ends with channel c in agg[0]
#pragma unroll
    for (int sh = 16; sh >= 1; sh >>= 1) {
        bool up = (lane & sh) != 0;
#pragma unroll
        for (int j = 0; j < sh; j++) {
            float send = up ? agg[j] : agg[j + sh];
            float got  = __shfl_xor_sync(0xffffffffu, send, sh);
            agg[j] = (up ? agg[j + sh] : agg[j]) + got;
        }
    }
    // gate + store (coalesced: lane = channel)
    float gv = agg[0] * g_uup[(n * HW + p) * 256 + head * 32 + lane];
    g_gated[(n * HW + p) * 256 + head * 32 + lane] = gv;

    // cooperative coalesced attn write
    __syncthreads();
    float* dst = attn_out + (size_t)nh * WS2 * HW + y0 * IMG_W;
    for (int i = tid; i < WS2 * IMG_W; i += 960) {
        int o = i / IMG_W, px = i - o * IMG_W;
        dst[(size_t)o * HW + px] = a_buf[px * WS2 + o];
    }
}

// ---------------- depthwise 5x5 conv (pad 2, no bias), channel-fastest -----
__global__ void k_dw(const float* __restrict__ Wdw) {
    int i = blockIdx.x * 256 + threadIdx.x;
    if (i >= NBATCH * 256 * HW) return;
    int c = i & 255;
    int p = (i >> 8) % HW;
    int n = i / (256 * HW);
    int y = p / IMG_W, x = p - y * IMG_W;
    const float* src = g_gated + (size_t)n * HW * 256;
    const float* wgt = Wdw + c * 25;
    float sum = 0.f;
#pragma unroll
    for (int ky = 0; ky < 5; ky++) {
        int ny = y + ky - 2;
        if (ny < 0 || ny >= IMG_H) continue;
#pragma unroll
        for (int kx = 0; kx < 5; kx++) {
            int nx = x + kx - 2;
            if (nx < 0 || nx >= IMG_W) continue;
            sum += wgt[ky * 5 + kx] * src[(ny * IMG_W + nx) * 256 + c];
        }
    }
    g_dw[(n * 256 + c) * HW + p] = sum;   // [c][p] layout for proj
}

// ---------------- final projection (M=128,K=256) ---------------------------
__global__ void k_proj(const float* __restrict__ Wproj, const float* __restrict__ bproj,
                       float* __restrict__ out) {
    __shared__ float Ws[32][64];
    __shared__ float Xs[32][64];
    int n = blockIdx.z;
    int o0 = blockIdx.y * 64, p0 = blockIdx.x * 64;
    const float* X = g_dw + n * 256 * HW;
    float acc[4][4];
#pragma unroll
    for (int i = 0; i < 4; i++)
#pragma unroll
        for (int j = 0; j < 4; j++) acc[i][j] = 0.f;
    int tx = threadIdx.x & 15, ty = threadIdx.x >> 4;
    for (int c0 = 0; c0 < 256; c0 += 32) {
        for (int i = threadIdx.x; i < 2048; i += 256) {
            int c = i & 31, o = i >> 5;
            Ws[c][o] = Wproj[(o0 + o) * 256 + c0 + c];
        }
        for (int i = threadIdx.x; i < 2048; i += 256) {
            int p = i & 63, c = i >> 6;
            int pp = p0 + p;
            Xs[c][p] = (pp < HW) ? X[(c0 + c) * HW + pp] : 0.f;
        }
        __syncthreads();
#pragma unroll
        for (int c = 0; c < 32; c++) {
            float4 a4 = *reinterpret_cast<const float4*>(&Ws[c][ty * 4]);
            float4 b4 = *reinterpret_cast<const float4*>(&Xs[c][tx * 4]);
            float a[4] = {a4.x, a4.y, a4.z, a4.w};
            float b[4] = {b4.x, b4.y, b4.z, b4.w};
#pragma unroll
            for (int i = 0; i < 4; i++)
#pragma unroll
                for (int j = 0; j < 4; j++) acc[i][j] += a[i] * b[j];
        }
        __syncthreads();
    }
#pragma unroll
    for (int i = 0; i < 4; i++) {
        int o = o0 + ty * 4 + i;
        float bb = bproj[o];
#pragma unroll
        for (int j = 0; j < 4; j++) {
            int p = p0 + tx * 4 + j;
            if (p < HW) out[p * (NBATCH * 128) + n * 128 + o] = acc[i][j] + bb;
        }
    }
}

// ---------------------------------------------------------------------------
extern "C" void kernel_launch(void* const* d_in, const int* in_sizes, int n_in,
                              void* d_out, int out_size) {
    const float* q     = (const float*)d_in[0];
    // d_in[1] = k : unused (overwritten by linear_QK(q) in the reference)
    const float* v     = (const float*)d_in[2];
    const float* u     = (const float*)d_in[3];
    const float* Wqk   = (const float*)d_in[4];
    const float* bqk   = (const float*)d_in[5];
    const float* Wv    = (const float*)d_in[6];
    const float* bv    = (const float*)d_in[7];
    const float* Wu    = (const float*)d_in[8];
    const float* bu    = (const float*)d_in[9];
    const float* Wrel  = (const float*)d_in[10];
    const float* brel  = (const float*)d_in[11];
    const float* Wdw   = (const float*)d_in[12];
    const float* Wproj = (const float*)d_in[13];
    const float* bproj = (const float*)d_in[14];
    float* out = (float*)d_out;

    const int OUT0 = HW * NBATCH * 128;                 // 230400
    const int OUT1 = NBATCH * NHEAD * WS2 * HW;         // 3240000
    int use_ext = (out_size >= OUT0 + OUT1) ? 1 : 0;

    float* attn_dst;
    if (use_ext) attn_dst = out + OUT0;
    else         cudaGetSymbolAddress((void**)&attn_dst, g_attn_fb);

    const int rel_smem  = (32 * 60 + 60 * WS2) * (int)sizeof(float);   // 61680
    const int attn_smem = (64 * TPIX + 30 * WS2) * (int)sizeof(float); // 149880
    cudaFuncSetAttribute(k_rel,  cudaFuncAttributeMaxDynamicSharedMemorySize, rel_smem);
    cudaFuncSetAttribute(k_attn, cudaFuncAttributeMaxDynamicSharedMemorySize, attn_smem);

    k_qkf <<<dim3(15, 4, 2), 256>>>(q, Wqk, bqk);
    k_vu  <<<dim3(15, 2, 8), 256>>>(v, u, Wv, bv, Wu, bu);
    k_rel <<<dim3(15, 16),   256, rel_smem>>>(Wrel, brel);
    k_attn<<<dim3(30, 8, 2), 960, attn_smem>>>(attn_dst);
    k_dw  <<<dim3((NBATCH * 256 * HW + 255) / 256), 256>>>(Wdw);
    k_proj<<<dim3(15, 2, 2), 256>>>(Wproj, bproj, out);
}

// round 3
// speedup vs baseline: 2.8592x; 1.2370x over previous
#include <cuda_runtime.h>

// Problem constants
#define HW     900
#define IMG_H  30
#define IMG_W  30
#define NBATCH 2
#define NHEAD  8
#define WS2    225
#define INVT   0.17677669529663687f   // 1/sqrt(32)

#define TROW   32                      // padded tile row stride
#define TPIX   (15 * TROW)             // 480 smem pixels per channel-quad

// ---------------- scratch (device globals: no allocation allowed) ----------
__device__ float g_qkf   [NBATCH * 256 * HW];            // [n][c][p]
__device__ float g_vvp   [NBATCH * 256 * HW];            // [n][c][p]
__device__ float g_uup   [NBATCH * HW * 256];            // [n][p][c]
__device__ float g_rel   [NBATCH * NHEAD * HW * WS2];    // [nh][p][o]
__device__ float g_gated [NBATCH * HW * 256];            // [n][p][c]
__device__ float g_dwp   [NBATCH * HW * 256];            // [n][p][c]
__device__ float g_attn_fb[NBATCH * NHEAD * WS2 * HW];

// ---------------- qk_feat = Wqk @ q + bqk  (M=256,K=256,P=900, batch 2) ----
__global__ void k_qkf(const float* __restrict__ q, const float* __restrict__ Wqk,
                      const float* __restrict__ bqk) {
    __shared__ float Ws[32][64];
    __shared__ float Xs[32][64];
    int n  = blockIdx.z;
    int o0 = blockIdx.y * 64, p0 = blockIdx.x * 64;
    const float* X = q + n * 256 * HW;
    float acc[4][4];
#pragma unroll
    for (int i = 0; i < 4; i++)
#pragma unroll
        for (int j = 0; j < 4; j++) acc[i][j] = 0.f;
    int tx = threadIdx.x & 15, ty = threadIdx.x >> 4;
    for (int c0 = 0; c0 < 256; c0 += 32) {
        for (int i = threadIdx.x; i < 2048; i += 256) {
            int c = i & 31, o = i >> 5;
            Ws[c][o] = Wqk[(o0 + o) * 256 + c0 + c];
        }
        for (int i = threadIdx.x; i < 2048; i += 256) {
            int p = i & 63, c = i >> 6;
            int pp = p0 + p;
            Xs[c][p] = (pp < HW) ? X[(c0 + c) * HW + pp] : 0.f;
        }
        __syncthreads();
#pragma unroll
        for (int c = 0; c < 32; c++) {
            float4 a4 = *reinterpret_cast<const float4*>(&Ws[c][ty * 4]);
            float4 b4 = *reinterpret_cast<const float4*>(&Xs[c][tx * 4]);
            float a[4] = {a4.x, a4.y, a4.z, a4.w};
            float b[4] = {b4.x, b4.y, b4.z, b4.w};
#pragma unroll
            for (int i = 0; i < 4; i++)
#pragma unroll
                for (int j = 0; j < 4; j++) acc[i][j] += a[i] * b[j];
        }
        __syncthreads();
    }
#pragma unroll
    for (int i = 0; i < 4; i++) {
        int o = o0 + ty * 4 + i;
        float bb = bqk[o];
#pragma unroll
        for (int j = 0; j < 4; j++) {
            int p = p0 + tx * 4 + j;
            if (p < HW) g_qkf[(n * 256 + o) * HW + p] = acc[i][j] + bb;
        }
    }
}

// ---------------- grouped 1x1 conv + SiLU + head interleave (v and u) ------
// grid.z: n*4 + which*2 + g   (which: 0=v, 1=u; g: group)
__global__ void k_vu(const float* __restrict__ v, const float* __restrict__ u,
                     const float* __restrict__ Wv, const float* __restrict__ bv,
                     const float* __restrict__ Wu, const float* __restrict__ bu) {
    __shared__ float Ws[32][64];
    __shared__ float Xs[32][64];
    __shared__ float Su[64][68];       // [p_local][o_local] staging for uup
    int z = blockIdx.z;
    int n = z >> 2, which = (z >> 1) & 1, g = z & 1;
    const float* src  = (which ? u  : v ) + (n * 256 + g * 128) * HW;
    const float* W    = (which ? Wu : Wv) + g * 128 * 128;
    const float* bias = (which ? bu : bv) + g * 128;
    int o0 = blockIdx.y * 64, p0 = blockIdx.x * 64;
    float acc[4][4];
#pragma unroll
    for (int i = 0; i < 4; i++)
#pragma unroll
        for (int j = 0; j < 4; j++) acc[i][j] = 0.f;
    int tx = threadIdx.x & 15, ty = threadIdx.x >> 4;
    for (int c0 = 0; c0 < 128; c0 += 32) {
        for (int i = threadIdx.x; i < 2048; i += 256) {
            int c = i & 31, o = i >> 5;
            Ws[c][o] = W[(o0 + o) * 128 + c0 + c];
        }
        for (int i = threadIdx.x; i < 2048; i += 256) {
            int p = i & 63, c = i >> 6;
            int pp = p0 + p;
            Xs[c][p] = (pp < HW) ? src[(c0 + c) * HW + pp] : 0.f;
        }
        __syncthreads();
#pragma unroll
        for (int c = 0; c < 32; c++) {
            float4 a4 = *reinterpret_cast<const float4*>(&Ws[c][ty * 4]);
            float4 b4 = *reinterpret_cast<const float4*>(&Xs[c][tx * 4]);
            float a[4] = {a4.x, a4.y, a4.z, a4.w};
            float b[4] = {b4.x, b4.y, b4.z, b4.w};
#pragma unroll
            for (int i = 0; i < 4; i++)
#pragma unroll
                for (int j = 0; j < 4; j++) acc[i][j] += a[i] * b[j];
        }
        __syncthreads();
    }
    if (!which) {
        // vv: [n][c][p] direct coalesced store
#pragma unroll
        for (int i = 0; i < 4; i++) {
            int o = o0 + ty * 4 + i;
            float bb = bias[o];
            int head = o >> 4, c16 = o & 15;
            int d = head * 32 + g * 16 + c16;
#pragma unroll
            for (int j = 0; j < 4; j++) {
                int p = p0 + tx * 4 + j;
                if (p < HW) {
                    float val = acc[i][j] + bb;
                    val = val / (1.f + __expf(-val));
                    g_vvp[(n * 256 + d) * HW + p] = val;
                }
            }
        }
    } else {
        // uu: stage [p][o] tile in smem, write [n][p][c] coalesced
#pragma unroll
        for (int i = 0; i < 4; i++) {
            int o = o0 + ty * 4 + i;
            float bb = bias[o];
#pragma unroll
            for (int j = 0; j < 4; j++) {
                float val = acc[i][j] + bb;
                Su[tx * 4 + j][ty * 4 + i] = val / (1.f + __expf(-val));
            }
        }
        __syncthreads();
        for (int idx = threadIdx.x; idx < 4096; idx += 256) {
            int pl = idx >> 6, ol = idx & 63;
            int p = p0 + pl;
            if (p < HW) {
                int o = o0 + ol;
                int d = (o >> 4) * 32 + g * 16 + (o & 15);
                g_uup[(n * HW + p) * 256 + d] = Su[pl][ol];
            }
        }
    }
}

// ---------------- rel = Wrel[head] @ qh + brel -> [nh][p][o] layout --------
__global__ void k_rel(const float* __restrict__ Wrel, const float* __restrict__ brel) {
    extern __shared__ float rsm[];
    float* Xs  = rsm;           // [32][60]
    float* Ssm = rsm + 32 * 60; // [60][225]
    int nh = blockIdx.y;
    int n = nh >> 3, head = nh & 7;
    int p0 = blockIdx.x * 60;
    int tid = threadIdx.x;
    for (int i = tid; i < 32 * 60; i += 256) {
        int c = i / 60, px = i - c * 60;
        Xs[c * 60 + px] = g_qkf[(n * 256 + head * 32 + c) * HW + p0 + px];
    }
    __syncthreads();
    int o = tid;
    if (o < WS2) {
        float w[32];
#pragma unroll
        for (int c = 0; c < 32; c++) w[c] = Wrel[(head * WS2 + o) * 32 + c];
        float bb = brel[head * WS2 + o];
        for (int pq = 0; pq < 15; pq++) {
            float4 acc = {bb, bb, bb, bb};
#pragma unroll
            for (int c = 0; c < 32; c++) {
                float4 xq = *reinterpret_cast<const float4*>(&Xs[c * 60 + pq * 4]);
                acc.x += w[c] * xq.x; acc.y += w[c] * xq.y;
                acc.z += w[c] * xq.z; acc.w += w[c] * xq.w;
            }
            Ssm[(pq * 4 + 0) * WS2 + o] = acc.x;
            Ssm[(pq * 4 + 1) * WS2 + o] = acc.y;
            Ssm[(pq * 4 + 2) * WS2 + o] = acc.z;
            Ssm[(pq * 4 + 3) * WS2 + o] = acc.w;
        }
    }
    __syncthreads();
    float* dst = g_rel + (size_t)(nh * HW + p0) * WS2;
    for (int i = tid; i < 60 * WS2; i += 256) dst[i] = Ssm[i];
}

// ---------------- fused windowed attention: warp-per-pixel, float4 smem ----
// grid (30 rows, 8 heads, 2 batch), block 960 (warp = pixel)
__global__ void __launch_bounds__(960, 1) k_attn(float* __restrict__ attn_out) {
    extern __shared__ float sm[];
    float4* k4   = reinterpret_cast<float4*>(sm);            // [8][TPIX]
    float4* v4   = k4 + 8 * TPIX;                            // [8][TPIX]
    float*  a_buf = sm + 2 * 4 * 8 * TPIX;                   // [30][225]
    int y0 = blockIdx.x, head = blockIdx.y, n = blockIdx.z;
    int nh = n * NHEAD + head;
    const float* qf = g_qkf + (n * 256 + head * 32) * HW;
    const float* vv = g_vvp + (n * 256 + head * 32) * HW;
    int tid = threadIdx.x;

    // load k and v tiles as channel-quads (rows y0-7..y0+7, zeros outside)
    for (int i = tid; i < 8 * TPIX; i += 960) {
        int c4 = i / TPIX, idx = i - c4 * TPIX;
        int ty = idx >> 5, nx = idx & 31;
        int gy = y0 - 7 + ty;
        float4 kk = {0.f, 0.f, 0.f, 0.f}, vk = {0.f, 0.f, 0.f, 0.f};
        if (gy >= 0 && gy < IMG_H && nx < IMG_W) {
            int gp = gy * IMG_W + nx;
            int cb = c4 * 4;
            kk.x = qf[(cb + 0) * HW + gp]; kk.y = qf[(cb + 1) * HW + gp];
            kk.z = qf[(cb + 2) * HW + gp]; kk.w = qf[(cb + 3) * HW + gp];
            vk.x = vv[(cb + 0) * HW + gp]; vk.y = vv[(cb + 1) * HW + gp];
            vk.z = vv[(cb + 2) * HW + gp]; vk.w = vv[(cb + 3) * HW + gp];
        }
        k4[i] = kk;
        v4[i] = vk;
    }
    __syncthreads();

    int w    = tid >> 5;   // warp = pixel x
    int lane = tid & 31;
    int x = w;
    int p = y0 * IMG_W + x;
    int qidx = 7 * TROW + x;   // smem index of own pixel

    const float* rel_p = g_rel + (size_t)(nh * HW + p) * WS2;

    // scores: 8 positions per lane, q re-read via broadcast LDS
    float sv[8];
    float m = -1e30f;
#pragma unroll
    for (int i = 0; i < 8; i++) {
        int o = i * 32 + lane;
        float s = -1e30f;
        if (o < WS2) {
            int oy = o / 15, ox = o - oy * 15;
            int ny = y0 + oy - 7;
            int nx = x + ox - 7;
            if (ny >= 0 && ny < IMG_H && nx >= 0 && nx < IMG_W) {
                int idx = oy * TROW + nx;
                float4 acc = {0.f, 0.f, 0.f, 0.f};
#pragma unroll
                for (int c4 = 0; c4 < 8; c4++) {
                    float4 qq = k4[c4 * TPIX + qidx];   // broadcast
                    float4 kk = k4[c4 * TPIX + idx];
                    acc.x += qq.x * kk.x; acc.y += qq.y * kk.y;
                    acc.z += qq.z * kk.z; acc.w += qq.w * kk.w;
                }
                s = ((acc.x + acc.y) + (acc.z + acc.w)) * INVT + rel_p[o];
            } else {
                s = -1e8f;   // masked: exp underflows to exactly 0
            }
        }
        sv[i] = s;
        m = fmaxf(m, s);
    }
#pragma unroll
    for (int sh = 16; sh; sh >>= 1) m = fmaxf(m, __shfl_xor_sync(0xffffffffu, m, sh));
    float l = 0.f;
    float av[8];
#pragma unroll
    for (int i = 0; i < 8; i++) { av[i] = __expf(sv[i] - m); l += av[i]; }
#pragma unroll
    for (int sh = 16; sh; sh >>= 1) l += __shfl_xor_sync(0xffffffffu, l, sh);
    float inv_l = 1.f / l;
#pragma unroll
    for (int i = 0; i < 8; i++) {
        av[i] *= inv_l;
        int o = i * 32 + lane;
        if (o < WS2) a_buf[x * WS2 + o] = av[i];
    }

    // aggregation
    float agg[32];
#pragma unroll
    for (int c = 0; c < 32; c++) agg[c] = 0.f;
#pragma unroll
    for (int i = 0; i < 8; i++) {
        int o = i * 32 + lane;
        if (o < WS2) {
            int oy = o / 15, ox = o - oy * 15;
            int ny = y0 + oy - 7;
            int nx = x + ox - 7;
            if (ny >= 0 && ny < IMG_H && nx >= 0 && nx < IMG_W) {
                int idx = oy * TROW + nx;
                float a = av[i];
#pragma unroll
                for (int c4 = 0; c4 < 8; c4++) {
                    float4 vk = v4[c4 * TPIX + idx];
                    agg[4 * c4 + 0] += a * vk.x;
                    agg[4 * c4 + 1] += a * vk.y;
                    agg[4 * c4 + 2] += a * vk.z;
                    agg[4 * c4 + 3] += a * vk.w;
                }
            }
        }
    }
    // butterfly reduce-scatter: lane c ends with channel c in agg[0]
#pragma unroll
    for (int sh = 16; sh >= 1; sh >>= 1) {
        bool up = (lane & sh) != 0;
#pragma unroll
        for (int j = 0; j < sh; j++) {
            float send = up ? agg[j] : agg[j + sh];
            float got  = __shfl_xor_sync(0xffffffffu, send, sh);
            agg[j] = (up ? agg[j + sh] : agg[j]) + got;
        }
    }
    float gv = agg[0] * g_uup[(n * HW + p) * 256 + head * 32 + lane];
    g_gated[(n * HW + p) * 256 + head * 32 + lane] = gv;

    __syncthreads();
    float* dst = attn_out + (size_t)nh * WS2 * HW + y0 * IMG_W;
    for (int i = tid; i < WS2 * IMG_W; i += 960) {
        int o = i / IMG_W, px = i - o * IMG_W;
        dst[(size_t)o * HW + px] = a_buf[px * WS2 + o];
    }
}

// ---------------- depthwise 5x5 conv (pad 2), [p][c] in and out ------------
__global__ void k_dw(const float* __restrict__ Wdw) {
    int i = blockIdx.x * 256 + threadIdx.x;
    if (i >= NBATCH * 256 * HW) return;
    int c = i & 255;
    int p = (i >> 8) % HW;
    int n = i / (256 * HW);
    int y = p / IMG_W, x = p - y * IMG_W;
    const float* src = g_gated + (size_t)n * HW * 256;
    const float* wgt = Wdw + c * 25;
    float sum = 0.f;
#pragma unroll
    for (int ky = 0; ky < 5; ky++) {
        int ny = y + ky - 2;
        if (ny < 0 || ny >= IMG_H) continue;
#pragma unroll
        for (int kx = 0; kx < 5; kx++) {
            int nx = x + kx - 2;
            if (nx < 0 || nx >= IMG_W) continue;
            sum += wgt[ky * 5 + kx] * src[(ny * IMG_W + nx) * 256 + c];
        }
    }
    g_dwp[(n * HW + p) * 256 + c] = sum;   // [p][c], coalesced
}

// ---------------- final projection (M=128,K=256), X read from [p][c] -------
__global__ void k_proj(const float* __restrict__ Wproj, const float* __restrict__ bproj,
                       float* __restrict__ out) {
    __shared__ float Ws[32][64];
    __shared__ float Xs[32 * 68];      // [c][p], row stride 68
    int n = blockIdx.z;
    int o0 = blockIdx.y * 64, p0 = blockIdx.x * 64;
    const float* X = g_dwp + (size_t)n * HW * 256;
    float acc[4][4];
#pragma unroll
    for (int i = 0; i < 4; i++)
#pragma unroll
        for (int j = 0; j < 4; j++) acc[i][j] = 0.f;
    int tx = threadIdx.x & 15, ty = threadIdx.x >> 4;
    for (int c0 = 0; c0 < 256; c0 += 32) {
        for (int i = threadIdx.x; i < 2048; i += 256) {
            int c = i & 31, o = i >> 5;
            Ws[c][o] = Wproj[(o0 + o) * 256 + c0 + c];
        }
        for (int i = threadIdx.x; i < 512; i += 256) {   // 512 float4 loads
            int c4 = i & 7, p = i >> 3;
            int pp = p0 + p;
            float4 xv = {0.f, 0.f, 0.f, 0.f};
            if (pp < HW)
                xv = *reinterpret_cast<const float4*>(&X[pp * 256 + c0 + c4 * 4]);
            Xs[(c4 * 4 + 0) * 68 + p] = xv.x;
            Xs[(c4 * 4 + 1) * 68 + p] = xv.y;
            Xs[(c4 * 4 + 2) * 68 + p] = xv.z;
            Xs[(c4 * 4 + 3) * 68 + p] = xv.w;
        }
        __syncthreads();
#pragma unroll
        for (int c = 0; c < 32; c++) {
            float4 a4 = *reinterpret_cast<const float4*>(&Ws[c][ty * 4]);
            float4 b4 = *reinterpret_cast<const float4*>(&Xs[c * 68 + tx * 4]);
            float a[4] = {a4.x, a4.y, a4.z, a4.w};
            float b[4] = {b4.x, b4.y, b4.z, b4.w};
#pragma unroll
            for (int i = 0; i < 4; i++)
#pragma unroll
                for (int j = 0; j < 4; j++) acc[i][j] += a[i] * b[j];
        }
        __syncthreads();
    }
#pragma unroll
    for (int i = 0; i < 4; i++) {
        int o = o0 + ty * 4 + i;
        float bb = bproj[o];
#pragma unroll
        for (int j = 0; j < 4; j++) {
            int p = p0 + tx * 4 + j;
            if (p < HW) out[p * (NBATCH * 128) + n * 128 + o] = acc[i][j] + bb;
        }
    }
}

// ---------------------------------------------------------------------------
extern "C" void kernel_launch(void* const* d_in, const int* in_sizes, int n_in,
                              void* d_out, int out_size) {
    const float* q     = (const float*)d_in[0];
    const float* v     = (const float*)d_in[2];
    const float* u     = (const float*)d_in[3];
    const float* Wqk   = (const float*)d_in[4];
    const float* bqk   = (const float*)d_in[5];
    const float* Wv    = (const float*)d_in[6];
    const float* bv    = (const float*)d_in[7];
    const float* Wu    = (const float*)d_in[8];
    const float* bu    = (const float*)d_in[9];
    const float* Wrel  = (const float*)d_in[10];
    const float* brel  = (const float*)d_in[11];
    const float* Wdw   = (const float*)d_in[12];
    const float* Wproj = (const float*)d_in[13];
    const float* bproj = (const float*)d_in[14];
    float* out = (float*)d_out;

    const int OUT0 = HW * NBATCH * 128;                 // 230400
    const int OUT1 = NBATCH * NHEAD * WS2 * HW;         // 3240000
    int use_ext = (out_size >= OUT0 + OUT1) ? 1 : 0;

    float* attn_dst;
    if (use_ext) attn_dst = out + OUT0;
    else         cudaGetSymbolAddress((void**)&attn_dst, g_attn_fb);

    const int rel_smem  = (32 * 60 + 60 * WS2) * (int)sizeof(float);       // 61680
    const int attn_smem = (2 * 4 * 8 * TPIX + 30 * WS2) * (int)sizeof(float); // 149880
    cudaFuncSetAttribute(k_rel,  cudaFuncAttributeMaxDynamicSharedMemorySize, rel_smem);
    cudaFuncSetAttribute(k_attn, cudaFuncAttributeMaxDynamicSharedMemorySize, attn_smem);

    k_qkf <<<dim3(15, 4, 2), 256>>>(q, Wqk, bqk);
    k_vu  <<<dim3(15, 2, 8), 256>>>(v, u, Wv, bv, Wu, bu);
    k_rel <<<dim3(15, 16),   256, rel_smem>>>(Wrel, brel);
    k_attn<<<dim3(30, 8, 2), 960, attn_smem>>>(attn_dst);
    k_dw  <<<dim3((NBATCH * 256 * HW + 255) / 256), 256>>>(Wdw);
    k_proj<<<dim3(15, 2, 2), 256>>>(Wproj, bproj, out);
}

// round 4
// speedup vs baseline: 3.0975x; 1.0834x over previous
#include <cuda_runtime.h>

// Problem constants
#define HW     900
#define IMG_H  30
#define IMG_W  30
#define NBATCH 2
#define NHEAD  8
#define WS2    225
#define INVT   0.17677669529663687f   // 1/sqrt(32)

#define TROW   32                      // padded tile row stride
#define TPIX   (15 * TROW)             // 480 smem pixels per channel-quad

// ---------------- scratch (device globals: no allocation allowed) ----------
__device__ float g_qkf   [NBATCH * 256 * HW];            // [n][c][p]
__device__ float g_vvp   [NBATCH * 256 * HW];            // [n][c][p]
__device__ float g_uup   [NBATCH * HW * 256];            // [n][p][c]
__device__ float g_gated [NBATCH * HW * 256];            // [n][p][c]
__device__ float g_dwp   [NBATCH * HW * 256];            // [n][p][c]
__device__ float g_attn_fb[NBATCH * NHEAD * WS2 * HW];

// ---------------- fused pre-GEMMs: qkf, v, u in one launch ------------------
// grid (15 p-tiles, 24): y<8 -> qkf (n = y>>2, o-tile = y&3)
//                        y>=8 -> vu  (idx=y-8: o-tile, g, which, n bits)
__global__ void k_pre(const float* __restrict__ q, const float* __restrict__ v,
                      const float* __restrict__ u,
                      const float* __restrict__ Wqk, const float* __restrict__ bqk,
                      const float* __restrict__ Wv,  const float* __restrict__ bv,
                      const float* __restrict__ Wu,  const float* __restrict__ bu) {
    __shared__ float Ws[32][64];
    __shared__ float Xs[32][64];
    __shared__ float Su[64][68];
    int p0 = blockIdx.x * 64;
    int yb = blockIdx.y;

    const float *src, *W, *bias;
    int KTOT, o0, n, g = 0, mode;     // mode: 0=qkf, 1=v, 2=u
    if (yb < 8) {
        n = yb >> 2; o0 = (yb & 3) * 64;
        src = q + n * 256 * HW; W = Wqk; bias = bqk; KTOT = 256; mode = 0;
    } else {
        int idx = yb - 8;
        o0 = (idx & 1) * 64;
        g = (idx >> 1) & 1;
        int which = (idx >> 2) & 1;
        n = (idx >> 3) & 1;
        src  = (which ? u  : v ) + (n * 256 + g * 128) * HW;
        W    = (which ? Wu : Wv) + g * 128 * 128;
        bias = (which ? bu : bv) + g * 128;
        KTOT = 128; mode = which ? 2 : 1;
    }

    float acc[4][4];
#pragma unroll
    for (int i = 0; i < 4; i++)
#pragma unroll
        for (int j = 0; j < 4; j++) acc[i][j] = 0.f;
    int tx = threadIdx.x & 15, ty = threadIdx.x >> 4;
    for (int c0 = 0; c0 < KTOT; c0 += 32) {
        for (int i = threadIdx.x; i < 2048; i += 256) {
            int c = i & 31, o = i >> 5;
            Ws[c][o] = W[(o0 + o) * KTOT + c0 + c];
        }
        for (int i = threadIdx.x; i < 2048; i += 256) {
            int p = i & 63, c = i >> 6;
            int pp = p0 + p;
            Xs[c][p] = (pp < HW) ? src[(c0 + c) * HW + pp] : 0.f;
        }
        __syncthreads();
#pragma unroll
        for (int c = 0; c < 32; c++) {
            float4 a4 = *reinterpret_cast<const float4*>(&Ws[c][ty * 4]);
            float4 b4 = *reinterpret_cast<const float4*>(&Xs[c][tx * 4]);
            float a[4] = {a4.x, a4.y, a4.z, a4.w};
            float b[4] = {b4.x, b4.y, b4.z, b4.w};
#pragma unroll
            for (int i = 0; i < 4; i++)
#pragma unroll
                for (int j = 0; j < 4; j++) acc[i][j] += a[i] * b[j];
        }
        __syncthreads();
    }

    if (mode == 0) {
#pragma unroll
        for (int i = 0; i < 4; i++) {
            int o = o0 + ty * 4 + i;
            float bb = bias[o];
#pragma unroll
            for (int j = 0; j < 4; j++) {
                int p = p0 + tx * 4 + j;
                if (p < HW) g_qkf[(n * 256 + o) * HW + p] = acc[i][j] + bb;
            }
        }
    } else if (mode == 1) {
#pragma unroll
        for (int i = 0; i < 4; i++) {
            int o = o0 + ty * 4 + i;
            float bb = bias[o];
            int d = (o >> 4) * 32 + g * 16 + (o & 15);
#pragma unroll
            for (int j = 0; j < 4; j++) {
                int p = p0 + tx * 4 + j;
                if (p < HW) {
                    float val = acc[i][j] + bb;
                    val = val / (1.f + __expf(-val));
                    g_vvp[(n * 256 + d) * HW + p] = val;
                }
            }
        }
    } else {
#pragma unroll
        for (int i = 0; i < 4; i++) {
            int o = o0 + ty * 4 + i;
            float bb = bias[o];
#pragma unroll
            for (int j = 0; j < 4; j++) {
                float val = acc[i][j] + bb;
                Su[tx * 4 + j][ty * 4 + i] = val / (1.f + __expf(-val));
            }
        }
        __syncthreads();
        for (int idx = threadIdx.x; idx < 4096; idx += 256) {
            int pl = idx >> 6, ol = idx & 63;
            int p = p0 + pl;
            if (p < HW) {
                int o = o0 + ol;
                int d = (o >> 4) * 32 + g * 16 + (o & 15);
                g_uup[(n * HW + p) * 256 + d] = Su[pl][ol];
            }
        }
    }
}

// ---------------- fused windowed attention (rel computed in-kernel) --------
// grid (30 rows, 8 heads, 2 batch), block 960 (warp = pixel)
__global__ void __launch_bounds__(960, 1) k_attn(float* __restrict__ attn_out,
                                                 const float* __restrict__ Wrel,
                                                 const float* __restrict__ brel) {
    extern __shared__ float sm[];
    float4* k4    = reinterpret_cast<float4*>(sm);           // [8][TPIX]
    float4* v4    = k4 + 8 * TPIX;                           // [8][TPIX]
    float4* Wrs   = v4 + 8 * TPIX;                           // [8][225]
    float*  brs   = sm + (2 * 8 * TPIX + 8 * WS2) * 4;       // [225]
    float*  a_buf = brs + WS2;                               // [30][225]
    int y0 = blockIdx.x, head = blockIdx.y, n = blockIdx.z;
    int nh = n * NHEAD + head;
    const float* qf = g_qkf + (n * 256 + head * 32) * HW;
    const float* vv = g_vvp + (n * 256 + head * 32) * HW;
    int tid = threadIdx.x;

    // stage Wrel[head] transposed: Wrs[c4][o] = channels 4c4..4c4+3 of offset o
    for (int i = tid; i < 8 * WS2; i += 960) {
        int o = i >> 3, c4 = i & 7;
        float4 w = *reinterpret_cast<const float4*>(&Wrel[(head * WS2 + o) * 32 + c4 * 4]);
        Wrs[c4 * WS2 + o] = w;
    }
    for (int i = tid; i < WS2; i += 960) brs[i] = brel[head * WS2 + i];

    // load k and v tiles as channel-quads (rows y0-7..y0+7, zeros outside)
    for (int i = tid; i < 8 * TPIX; i += 960) {
        int c4 = i / TPIX, idx = i - c4 * TPIX;
        int ty = idx >> 5, nx = idx & 31;
        int gy = y0 - 7 + ty;
        float4 kk = {0.f, 0.f, 0.f, 0.f}, vk = {0.f, 0.f, 0.f, 0.f};
        if (gy >= 0 && gy < IMG_H && nx < IMG_W) {
            int gp = gy * IMG_W + nx;
            int cb = c4 * 4;
            kk.x = qf[(cb + 0) * HW + gp]; kk.y = qf[(cb + 1) * HW + gp];
            kk.z = qf[(cb + 2) * HW + gp]; kk.w = qf[(cb + 3) * HW + gp];
            vk.x = vv[(cb + 0) * HW + gp]; vk.y = vv[(cb + 1) * HW + gp];
            vk.z = vv[(cb + 2) * HW + gp]; vk.w = vv[(cb + 3) * HW + gp];
        }
        k4[i] = kk;
        v4[i] = vk;
    }
    __syncthreads();

    int w    = tid >> 5;   // warp = pixel x
    int lane = tid & 31;
    int x = w;
    int p = y0 * IMG_W + x;
    int qidx = 7 * TROW + x;   // smem index of own pixel

    // scores: 8 positions per lane; rel fused (q unscaled dot Wrel)
    float sv[8];
    float m = -1e30f;
#pragma unroll
    for (int i = 0; i < 8; i++) {
        int o = i * 32 + lane;
        float s = -1e30f;
        if (o < WS2) {
            int oy = o / 15, ox = o - oy * 15;
            int ny = y0 + oy - 7;
            int nx = x + ox - 7;
            if (ny >= 0 && ny < IMG_H && nx >= 0 && nx < IMG_W) {
                int idx = oy * TROW + nx;
                float4 acc = {0.f, 0.f, 0.f, 0.f};
                float4 rc  = {0.f, 0.f, 0.f, 0.f};
#pragma unroll
                for (int c4 = 0; c4 < 8; c4++) {
                    float4 qq = k4[c4 * TPIX + qidx];   // broadcast
                    float4 kk = k4[c4 * TPIX + idx];
                    float4 wr = Wrs[c4 * WS2 + o];
                    acc.x += qq.x * kk.x; acc.y += qq.y * kk.y;
                    acc.z += qq.z * kk.z; acc.w += qq.w * kk.w;
                    rc.x  += qq.x * wr.x; rc.y  += qq.y * wr.y;
                    rc.z  += qq.z * wr.z; rc.w  += qq.w * wr.w;
                }
                s = ((acc.x + acc.y) + (acc.z + acc.w)) * INVT
                  + ((rc.x + rc.y) + (rc.z + rc.w)) + brs[o];
            } else {
                s = -1e8f;   // masked: exp underflows to exactly 0
            }
        }
        sv[i] = s;
        m = fmaxf(m, s);
    }
#pragma unroll
    for (int sh = 16; sh; sh >>= 1) m = fmaxf(m, __shfl_xor_sync(0xffffffffu, m, sh));
    float l = 0.f;
    float av[8];
#pragma unroll
    for (int i = 0; i < 8; i++) { av[i] = __expf(sv[i] - m); l += av[i]; }
#pragma unroll
    for (int sh = 16; sh; sh >>= 1) l += __shfl_xor_sync(0xffffffffu, l, sh);
    float inv_l = 1.f / l;
#pragma unroll
    for (int i = 0; i < 8; i++) {
        av[i] *= inv_l;
        int o = i * 32 + lane;
        if (o < WS2) a_buf[x * WS2 + o] = av[i];
    }

    // aggregation
    float agg[32];
#pragma unroll
    for (int c = 0; c < 32; c++) agg[c] = 0.f;
#pragma unroll
    for (int i = 0; i < 8; i++) {
        int o = i * 32 + lane;
        if (o < WS2) {
            int oy = o / 15, ox = o - oy * 15;
            int ny = y0 + oy - 7;
            int nx = x + ox - 7;
            if (ny >= 0 && ny < IMG_H && nx >= 0 && nx < IMG_W) {
                int idx = oy * TROW + nx;
                float a = av[i];
#pragma unroll
                for (int c4 = 0; c4 < 8; c4++) {
                    float4 vk = v4[c4 * TPIX + idx];
                    agg[4 * c4 + 0] += a * vk.x;
                    agg[4 * c4 + 1] += a * vk.y;
                    agg[4 * c4 + 2] += a * vk.z;
                    agg[4 * c4 + 3] += a * vk.w;
                }
            }
        }
    }
    // butterfly reduce-scatter: lane c ends with channel c in agg[0]
#pragma unroll
    for (int sh = 16; sh >= 1; sh >>= 1) {
        bool up = (lane & sh) != 0;
#pragma unroll
        for (int j = 0; j < sh; j++) {
            float send = up ? agg[j] : agg[j + sh];
            float got  = __shfl_xor_sync(0xffffffffu, send, sh);
            agg[j] = (up ? agg[j + sh] : agg[j]) + got;
        }
    }
    float gv = agg[0] * g_uup[(n * HW + p) * 256 + head * 32 + lane];
    g_gated[(n * HW + p) * 256 + head * 32 + lane] = gv;

    __syncthreads();
    float* dst = attn_out + (size_t)nh * WS2 * HW + y0 * IMG_W;
    for (int i = tid; i < WS2 * IMG_W; i += 960) {
        int o = i / IMG_W, px = i - o * IMG_W;
        dst[(size_t)o * HW + px] = a_buf[px * WS2 + o];
    }
}

// ---------------- depthwise 5x5 conv (pad 2), [p][c] in and out ------------
__global__ void k_dw(const float* __restrict__ Wdw) {
    int i = blockIdx.x * 256 + threadIdx.x;
    if (i >= NBATCH * 256 * HW) return;
    int c = i & 255;
    int p = (i >> 8) % HW;
    int n = i / (256 * HW);
    int y = p / IMG_W, x = p - y * IMG_W;
    const float* src = g_gated + (size_t)n * HW * 256;
    const float* wgt = Wdw + c * 25;
    float sum = 0.f;
#pragma unroll
    for (int ky = 0; ky < 5; ky++) {
        int ny = y + ky - 2;
        if (ny < 0 || ny >= IMG_H) continue;
#pragma unroll
        for (int kx = 0; kx < 5; kx++) {
            int nx = x + kx - 2;
            if (nx < 0 || nx >= IMG_W) continue;
            sum += wgt[ky * 5 + kx] * src[(ny * IMG_W + nx) * 256 + c];
        }
    }
    g_dwp[(n * HW + p) * 256 + c] = sum;   // [p][c], coalesced
}

// ---------------- final projection (M=128,K=256), X read from [p][c] -------
__global__ void k_proj(const float* __restrict__ Wproj, const float* __restrict__ bproj,
                       float* __restrict__ out) {
    __shared__ float Ws[32][64];
    __shared__ float Xs[32 * 68];      // [c][p], row stride 68
    int n = blockIdx.z;
    int o0 = blockIdx.y * 64, p0 = blockIdx.x * 64;
    const float* X = g_dwp + (size_t)n * HW * 256;
    float acc[4][4];
#pragma unroll
    for (int i = 0; i < 4; i++)
#pragma unroll
        for (int j = 0; j < 4; j++) acc[i][j] = 0.f;
    int tx = threadIdx.x & 15, ty = threadIdx.x >> 4;
    for (int c0 = 0; c0 < 256; c0 += 32) {
        for (int i = threadIdx.x; i < 2048; i += 256) {
            int c = i & 31, o = i >> 5;
            Ws[c][o] = Wproj[(o0 + o) * 256 + c0 + c];
        }
        for (int i = threadIdx.x; i < 512; i += 256) {
            int c4 = i & 7, p = i >> 3;
            int pp = p0 + p;
            float4 xv = {0.f, 0.f, 0.f, 0.f};
            if (pp < HW)
                xv = *reinterpret_cast<const float4*>(&X[pp * 256 + c0 + c4 * 4]);
            Xs[(c4 * 4 + 0) * 68 + p] = xv.x;
            Xs[(c4 * 4 + 1) * 68 + p] = xv.y;
            Xs[(c4 * 4 + 2) * 68 + p] = xv.z;
            Xs[(c4 * 4 + 3) * 68 + p] = xv.w;
        }
        __syncthreads();
#pragma unroll
        for (int c = 0; c < 32; c++) {
            float4 a4 = *reinterpret_cast<const float4*>(&Ws[c][ty * 4]);
            float4 b4 = *reinterpret_cast<const float4*>(&Xs[c * 68 + tx * 4]);
            float a[4] = {a4.x, a4.y, a4.z, a4.w};
            float b[4] = {b4.x, b4.y, b4.z, b4.w};
#pragma unroll
            for (int i = 0; i < 4; i++)
#pragma unroll
                for (int j = 0; j < 4; j++) acc[i][j] += a[i] * b[j];
        }
        __syncthreads();
    }
#pragma unroll
    for (int i = 0; i < 4; i++) {
        int o = o0 + ty * 4 + i;
        float bb = bproj[o];
#pragma unroll
        for (int j = 0; j < 4; j++) {
            int p = p0 + tx * 4 + j;
            if (p < HW) out[p * (NBATCH * 128) + n * 128 + o] = acc[i][j] + bb;
        }
    }
}

// ---------------------------------------------------------------------------
extern "C" void kernel_launch(void* const* d_in, const int* in_sizes, int n_in,
                              void* d_out, int out_size) {
    const float* q     = (const float*)d_in[0];
    const float* v     = (const float*)d_in[2];
    const float* u     = (const float*)d_in[3];
    const float* Wqk   = (const float*)d_in[4];
    const float* bqk   = (const float*)d_in[5];
    const float* Wv    = (const float*)d_in[6];
    const float* bv    = (const float*)d_in[7];
    const float* Wu    = (const float*)d_in[8];
    const float* bu    = (const float*)d_in[9];
    const float* Wrel  = (const float*)d_in[10];
    const float* brel  = (const float*)d_in[11];
    const float* Wdw   = (const float*)d_in[12];
    const float* Wproj = (const float*)d_in[13];
    const float* bproj = (const float*)d_in[14];
    float* out = (float*)d_out;

    const int OUT0 = HW * NBATCH * 128;                 // 230400
    const int OUT1 = NBATCH * NHEAD * WS2 * HW;         // 3240000
    int use_ext = (out_size >= OUT0 + OUT1) ? 1 : 0;

    float* attn_dst;
    if (use_ext) attn_dst = out + OUT0;
    else         cudaGetSymbolAddress((void**)&attn_dst, g_attn_fb);

    // k4+v4 (2*32*480) + Wrs (8*4*225) + brs (225) + a_buf (30*225) floats
    const int attn_smem = (2 * 32 * TPIX + 32 * WS2 + WS2 + 30 * WS2) * (int)sizeof(float);
    cudaFuncSetAttribute(k_attn, cudaFuncAttributeMaxDynamicSharedMemorySize, attn_smem);

    k_pre <<<dim3(15, 24),   256>>>(q, v, u, Wqk, bqk, Wv, bv, Wu, bu);
    k_attn<<<dim3(30, 8, 2), 960, attn_smem>>>(attn_dst, Wrel, brel);
    k_dw  <<<dim3((NBATCH * 256 * HW + 255) / 256), 256>>>(Wdw);
    k_proj<<<dim3(15, 2, 2), 256>>>(Wproj, bproj, out);
}

// round 5
// speedup vs baseline: 3.4645x; 1.1185x over previous
#include <cuda_runtime.h>

// Problem constants
#define HW     900
#define IMG_H  30
#define IMG_W  30
#define NBATCH 2
#define NHEAD  8
#define WS2    225
#define INVT   0.17677669529663687f   // 1/sqrt(32)

#define TROW   32                      // padded tile row stride
#define TPIX   (15 * TROW)             // 480 smem pixels per channel-quad

// ---------------- scratch (device globals: no allocation allowed) ----------
__device__ float g_qkf   [NBATCH * 256 * HW];            // [n][c][p]
__device__ float g_vvp   [NBATCH * 256 * HW];            // [n][c][p]
__device__ float g_uup   [NBATCH * HW * 256];            // [n][p][c]
__device__ float g_gated [NBATCH * HW * 256];            // [n][p][c]
__device__ float g_dwp   [NBATCH * HW * 256];            // [n][p][c]
__device__ float g_attn_fb[NBATCH * NHEAD * WS2 * HW];

// ---------------- fused pre-GEMMs: qkf, v, u in one launch ------------------
// grid (15 p-tiles, 24): y<8 -> qkf; y>=8 -> v/u grouped conv. Register-
// prefetched K loop: LDG for chunk c+1 overlaps compute of chunk c.
__global__ void k_pre(const float* __restrict__ q, const float* __restrict__ v,
                      const float* __restrict__ u,
                      const float* __restrict__ Wqk, const float* __restrict__ bqk,
                      const float* __restrict__ Wv,  const float* __restrict__ bv,
                      const float* __restrict__ Wu,  const float* __restrict__ bu) {
    __shared__ float Ws[32][64];
    __shared__ float Xs[32][64];
    __shared__ float Su[64][68];
    int p0 = blockIdx.x * 64;
    int yb = blockIdx.y;
    int tid = threadIdx.x;

    const float *src, *W, *bias;
    int KTOT, o0, n, g = 0, mode;     // mode: 0=qkf, 1=v, 2=u
    if (yb < 8) {
        n = yb >> 2; o0 = (yb & 3) * 64;
        src = q + n * 256 * HW; W = Wqk; bias = bqk; KTOT = 256; mode = 0;
    } else {
        int idx = yb - 8;
        o0 = (idx & 1) * 64;
        g = (idx >> 1) & 1;
        int which = (idx >> 2) & 1;
        n = (idx >> 3) & 1;
        src  = (which ? u  : v ) + (n * 256 + g * 128) * HW;
        W    = (which ? Wu : Wv) + g * 128 * 128;
        bias = (which ? bu : bv) + g * 128;
        KTOT = 128; mode = which ? 2 : 1;
    }

    float acc[4][4];
#pragma unroll
    for (int i = 0; i < 4; i++)
#pragma unroll
        for (int j = 0; j < 4; j++) acc[i][j] = 0.f;
    int tx = tid & 15, ty = tid >> 4;

    float wr[8], xr[8];
    // prefetch chunk 0
#pragma unroll
    for (int j = 0; j < 8; j++) {
        int i = tid + j * 256;
        wr[j] = W[((o0 + (i >> 5)) * KTOT) + (i & 31)];
        int pp = p0 + (i & 63);
        xr[j] = (pp < HW) ? src[(i >> 6) * HW + pp] : 0.f;
    }
    for (int c0 = 0; c0 < KTOT; c0 += 32) {
        // stage current chunk
#pragma unroll
        for (int j = 0; j < 8; j++) {
            int i = tid + j * 256;
            Ws[i & 31][i >> 5] = wr[j];
            Xs[i >> 6][i & 63] = xr[j];
        }
        __syncthreads();
        if (c0 + 32 < KTOT) {
            int c1 = c0 + 32;
#pragma unroll
            for (int j = 0; j < 8; j++) {
                int i = tid + j * 256;
                wr[j] = W[((o0 + (i >> 5)) * KTOT) + c1 + (i & 31)];
                int pp = p0 + (i & 63);
                xr[j] = (pp < HW) ? src[(c1 + (i >> 6)) * HW + pp] : 0.f;
            }
        }
#pragma unroll
        for (int c = 0; c < 32; c++) {
            float4 a4 = *reinterpret_cast<const float4*>(&Ws[c][ty * 4]);
            float4 b4 = *reinterpret_cast<const float4*>(&Xs[c][tx * 4]);
            float a[4] = {a4.x, a4.y, a4.z, a4.w};
            float b[4] = {b4.x, b4.y, b4.z, b4.w};
#pragma unroll
            for (int i = 0; i < 4; i++)
#pragma unroll
                for (int j = 0; j < 4; j++) acc[i][j] += a[i] * b[j];
        }
        __syncthreads();
    }

    if (mode == 0) {
#pragma unroll
        for (int i = 0; i < 4; i++) {
            int o = o0 + ty * 4 + i;
            float bb = bias[o];
#pragma unroll
            for (int j = 0; j < 4; j++) {
                int p = p0 + tx * 4 + j;
                if (p < HW) g_qkf[(n * 256 + o) * HW + p] = acc[i][j] + bb;
            }
        }
    } else if (mode == 1) {
#pragma unroll
        for (int i = 0; i < 4; i++) {
            int o = o0 + ty * 4 + i;
            float bb = bias[o];
            int d = (o >> 4) * 32 + g * 16 + (o & 15);
#pragma unroll
            for (int j = 0; j < 4; j++) {
                int p = p0 + tx * 4 + j;
                if (p < HW) {
                    float val = acc[i][j] + bb;
                    val = val / (1.f + __expf(-val));
                    g_vvp[(n * 256 + d) * HW + p] = val;
                }
            }
        }
    } else {
#pragma unroll
        for (int i = 0; i < 4; i++) {
            int o = o0 + ty * 4 + i;
            float bb = bias[o];
#pragma unroll
            for (int j = 0; j < 4; j++) {
                float val = acc[i][j] + bb;
                Su[tx * 4 + j][ty * 4 + i] = val / (1.f + __expf(-val));
            }
        }
        __syncthreads();
        for (int idx = tid; idx < 4096; idx += 256) {
            int pl = idx >> 6, ol = idx & 63;
            int p = p0 + pl;
            if (p < HW) {
                int o = o0 + ol;
                int d = (o >> 4) * 32 + g * 16 + (o & 15);
                g_uup[(n * HW + p) * 256 + d] = Su[pl][ol];
            }
        }
    }
}

// ---------------- fused windowed attention (rel computed in-kernel) --------
// grid (30 rows, 8 heads, 2 batch), block 960 (warp = pixel)
__global__ void __launch_bounds__(960, 1) k_attn(float* __restrict__ attn_out,
                                                 const float* __restrict__ Wrel,
                                                 const float* __restrict__ brel) {
    extern __shared__ float sm[];
    float4* k4    = reinterpret_cast<float4*>(sm);           // [8][TPIX]
    float4* v4    = k4 + 8 * TPIX;                           // [8][TPIX]
    float4* Wrs   = v4 + 8 * TPIX;                           // [8][225]
    float*  brs   = sm + (2 * 8 * TPIX + 8 * WS2) * 4;       // [225]
    float*  a_buf = brs + WS2;                               // [30][225]
    int y0 = blockIdx.x, head = blockIdx.y, n = blockIdx.z;
    int nh = n * NHEAD + head;
    const float* qf = g_qkf + (n * 256 + head * 32) * HW;
    const float* vv = g_vvp + (n * 256 + head * 32) * HW;
    int tid = threadIdx.x;

    for (int i = tid; i < 8 * WS2; i += 960) {
        int o = i >> 3, c4 = i & 7;
        float4 w = *reinterpret_cast<const float4*>(&Wrel[(head * WS2 + o) * 32 + c4 * 4]);
        Wrs[c4 * WS2 + o] = w;
    }
    for (int i = tid; i < WS2; i += 960) brs[i] = brel[head * WS2 + i];

    for (int i = tid; i < 8 * TPIX; i += 960) {
        int c4 = i / TPIX, idx = i - c4 * TPIX;
        int ty = idx >> 5, nx = idx & 31;
        int gy = y0 - 7 + ty;
        float4 kk = {0.f, 0.f, 0.f, 0.f}, vk = {0.f, 0.f, 0.f, 0.f};
        if (gy >= 0 && gy < IMG_H && nx < IMG_W) {
            int gp = gy * IMG_W + nx;
            int cb = c4 * 4;
            kk.x = qf[(cb + 0) * HW + gp]; kk.y = qf[(cb + 1) * HW + gp];
            kk.z = qf[(cb + 2) * HW + gp]; kk.w = qf[(cb + 3) * HW + gp];
            vk.x = vv[(cb + 0) * HW + gp]; vk.y = vv[(cb + 1) * HW + gp];
            vk.z = vv[(cb + 2) * HW + gp]; vk.w = vv[(cb + 3) * HW + gp];
        }
        k4[i] = kk;
        v4[i] = vk;
    }
    __syncthreads();

    int w    = tid >> 5;   // warp = pixel x
    int lane = tid & 31;
    int x = w;
    int p = y0 * IMG_W + x;
    int qidx = 7 * TROW + x;

    float sv[8];
    float m = -1e30f;
#pragma unroll
    for (int i = 0; i < 8; i++) {
        int o = i * 32 + lane;
        float s = -1e30f;
        if (o < WS2) {
            int oy = o / 15, ox = o - oy * 15;
            int ny = y0 + oy - 7;
            int nx = x + ox - 7;
            if (ny >= 0 && ny < IMG_H && nx >= 0 && nx < IMG_W) {
                int idx = oy * TROW + nx;
                float4 acc = {0.f, 0.f, 0.f, 0.f};
                float4 rc  = {0.f, 0.f, 0.f, 0.f};
#pragma unroll
                for (int c4 = 0; c4 < 8; c4++) {
                    float4 qq = k4[c4 * TPIX + qidx];   // broadcast
                    float4 kk = k4[c4 * TPIX + idx];
                    float4 wr = Wrs[c4 * WS2 + o];
                    acc.x += qq.x * kk.x; acc.y += qq.y * kk.y;
                    acc.z += qq.z * kk.z; acc.w += qq.w * kk.w;
                    rc.x  += qq.x * wr.x; rc.y  += qq.y * wr.y;
                    rc.z  += qq.z * wr.z; rc.w  += qq.w * wr.w;
                }
                s = ((acc.x + acc.y) + (acc.z + acc.w)) * INVT
                  + ((rc.x + rc.y) + (rc.z + rc.w)) + brs[o];
            } else {
                s = -1e8f;
            }
        }
        sv[i] = s;
        m = fmaxf(m, s);
    }
#pragma unroll
    for (int sh = 16; sh; sh >>= 1) m = fmaxf(m, __shfl_xor_sync(0xffffffffu, m, sh));
    float l = 0.f;
    float av[8];
#pragma unroll
    for (int i = 0; i < 8; i++) { av[i] = __expf(sv[i] - m); l += av[i]; }
#pragma unroll
    for (int sh = 16; sh; sh >>= 1) l += __shfl_xor_sync(0xffffffffu, l, sh);
    float inv_l = 1.f / l;
#pragma unroll
    for (int i = 0; i < 8; i++) {
        av[i] *= inv_l;
        int o = i * 32 + lane;
        if (o < WS2) a_buf[x * WS2 + o] = av[i];
    }

    float agg[32];
#pragma unroll
    for (int c = 0; c < 32; c++) agg[c] = 0.f;
#pragma unroll
    for (int i = 0; i < 8; i++) {
        int o = i * 32 + lane;
        if (o < WS2) {
            int oy = o / 15, ox = o - oy * 15;
            int ny = y0 + oy - 7;
            int nx = x + ox - 7;
            if (ny >= 0 && ny < IMG_H && nx >= 0 && nx < IMG_W) {
                int idx = oy * TROW + nx;
                float a = av[i];
#pragma unroll
                for (int c4 = 0; c4 < 8; c4++) {
                    float4 vk = v4[c4 * TPIX + idx];
                    agg[4 * c4 + 0] += a * vk.x;
                    agg[4 * c4 + 1] += a * vk.y;
                    agg[4 * c4 + 2] += a * vk.z;
                    agg[4 * c4 + 3] += a * vk.w;
                }
            }
        }
    }
#pragma unroll
    for (int sh = 16; sh >= 1; sh >>= 1) {
        bool up = (lane & sh) != 0;
#pragma unroll
        for (int j = 0; j < sh; j++) {
            float send = up ? agg[j] : agg[j + sh];
            float got  = __shfl_xor_sync(0xffffffffu, send, sh);
            agg[j] = (up ? agg[j + sh] : agg[j]) + got;
        }
    }
    float gv = agg[0] * g_uup[(n * HW + p) * 256 + head * 32 + lane];
    g_gated[(n * HW + p) * 256 + head * 32 + lane] = gv;

    __syncthreads();
    float* dst = attn_out + (size_t)nh * WS2 * HW + y0 * IMG_W;
    for (int i = tid; i < WS2 * IMG_W; i += 960) {
        int o = i / IMG_W, px = i - o * IMG_W;
        dst[(size_t)o * HW + px] = a_buf[px * WS2 + o];
    }
}

// ---------------- depthwise 5x5 conv, thread = (pixel, channel-quad) -------
// grid 450 blocks x 256 thr; weights staged transposed in smem.
__global__ void k_dw(const float* __restrict__ Wdw) {
    __shared__ float ws[25 * 256];     // [k][c]
    int tid = threadIdx.x;
    for (int i = tid; i < 25 * 256; i += 256) {
        int c = i / 25, k = i - c * 25;      // read Wdw coalesced-ish
        ws[k * 256 + c] = Wdw[i];
    }
    __syncthreads();
    int i = blockIdx.x * 256 + tid;
    int c4 = i & 63;
    int rest = i >> 6;
    int p = rest % HW;
    int n = rest / HW;
    int y = p / IMG_W, x = p - y * IMG_W;
    const float* src = g_gated + (size_t)n * HW * 256;
    float4 acc = {0.f, 0.f, 0.f, 0.f};
#pragma unroll
    for (int ky = 0; ky < 5; ky++) {
        int ny = y + ky - 2;
        if (ny < 0 || ny >= IMG_H) continue;
#pragma unroll
        for (int kx = 0; kx < 5; kx++) {
            int nx = x + kx - 2;
            if (nx < 0 || nx >= IMG_W) continue;
            int k = ky * 5 + kx;
            float4 gk = *reinterpret_cast<const float4*>(&src[(ny * IMG_W + nx) * 256 + c4 * 4]);
            float4 wv = *reinterpret_cast<const float4*>(&ws[k * 256 + c4 * 4]);
            acc.x += wv.x * gk.x; acc.y += wv.y * gk.y;
            acc.z += wv.z * gk.z; acc.w += wv.w * gk.w;
        }
    }
    *reinterpret_cast<float4*>(&g_dwp[((size_t)n * HW + p) * 256 + c4 * 4]) = acc;
}

// ---------------- final projection (M=128,K=256), double-buffered ----------
// grid (15 p-tiles of 64, 4 o-tiles of 32, 2 n), 256 threads
__global__ void k_proj(const float* __restrict__ Wproj, const float* __restrict__ bproj,
                       float* __restrict__ out) {
    __shared__ float Ws[2][32 * 34];   // [c][o], stride 34
    __shared__ float Xs[2][32 * 68];   // [c][p], stride 68
    int n = blockIdx.z;
    int o0 = blockIdx.y * 32, p0 = blockIdx.x * 64;
    const float* X = g_dwp + (size_t)n * HW * 256;
    int tid = threadIdx.x;
    int tx = tid & 15, ty = tid >> 4;
    float acc[2][4];
#pragma unroll
    for (int i = 0; i < 2; i++)
#pragma unroll
        for (int j = 0; j < 4; j++) acc[i][j] = 0.f;

    // prefetch regs: Ws chunk 1024 floats (1 float4/thr), Xs 2048 (2 float4/thr)
    int wo = tid >> 3, wc = (tid & 7) * 4;          // Ws: o (32), c-quad
    float4 wr, xr0, xr1;
    {
        wr = *reinterpret_cast<const float4*>(&Wproj[(o0 + wo) * 256 + wc]);
        int c40 = tid & 7,  pA = tid >> 3;          // Xs first half: p 0..31
        int pB = pA + 32;                           // second half
        int ppA = p0 + pA, ppB = p0 + pB;
        xr0 = (ppA < HW) ? *reinterpret_cast<const float4*>(&X[ppA * 256 + c40 * 4])
                         : make_float4(0.f, 0.f, 0.f, 0.f);
        xr1 = (ppB < HW) ? *reinterpret_cast<const float4*>(&X[ppB * 256 + c40 * 4])
                         : make_float4(0.f, 0.f, 0.f, 0.f);
    }
    int buf = 0;
    for (int c0 = 0; c0 < 256; c0 += 32) {
        // stage into buf
        Ws[buf][(wc + 0) * 34 + wo] = wr.x;
        Ws[buf][(wc + 1) * 34 + wo] = wr.y;
        Ws[buf][(wc + 2) * 34 + wo] = wr.z;
        Ws[buf][(wc + 3) * 34 + wo] = wr.w;
        {
            int c40 = tid & 7, pA = tid >> 3, pB = pA + 32;
            Xs[buf][(c40 * 4 + 0) * 68 + pA] = xr0.x;
            Xs[buf][(c40 * 4 + 1) * 68 + pA] = xr0.y;
            Xs[buf][(c40 * 4 + 2) * 68 + pA] = xr0.z;
            Xs[buf][(c40 * 4 + 3) * 68 + pA] = xr0.w;
            Xs[buf][(c40 * 4 + 0) * 68 + pB] = xr1.x;
            Xs[buf][(c40 * 4 + 1) * 68 + pB] = xr1.y;
            Xs[buf][(c40 * 4 + 2) * 68 + pB] = xr1.z;
            Xs[buf][(c40 * 4 + 3) * 68 + pB] = xr1.w;
        }
        __syncthreads();
        if (c0 + 32 < 256) {
            int c1 = c0 + 32;
            wr = *reinterpret_cast<const float4*>(&Wproj[(o0 + wo) * 256 + c1 + wc]);
            int c40 = tid & 7, pA = tid >> 3, pB = pA + 32;
            int ppA = p0 + pA, ppB = p0 + pB;
            xr0 = (ppA < HW) ? *reinterpret_cast<const float4*>(&X[ppA * 256 + c1 + c40 * 4])
                             : make_float4(0.f, 0.f, 0.f, 0.f);
            xr1 = (ppB < HW) ? *reinterpret_cast<const float4*>(&X[ppB * 256 + c1 + c40 * 4])
                             : make_float4(0.f, 0.f, 0.f, 0.f);
        }
#pragma unroll
        for (int c = 0; c < 32; c++) {
            float a0 = Ws[buf][c * 34 + ty * 2 + 0];
            float a1 = Ws[buf][c * 34 + ty * 2 + 1];
            float4 b4 = *reinterpret_cast<const float4*>(&Xs[buf][c * 68 + tx * 4]);
            acc[0][0] += a0 * b4.x; acc[0][1] += a0 * b4.y;
            acc[0][2] += a0 * b4.z; acc[0][3] += a0 * b4.w;
            acc[1][0] += a1 * b4.x; acc[1][1] += a1 * b4.y;
            acc[1][2] += a1 * b4.z; acc[1][3] += a1 * b4.w;
        }
        buf ^= 1;
        // no second sync needed: next stage writes to the other buffer, and the
        // __syncthreads() above (next iteration) orders stage-vs-compute.
    }
    __syncthreads();
#pragma unroll
    for (int i = 0; i < 2; i++) {
        int o = o0 + ty * 2 + i;
        float bb = bproj[o];
#pragma unroll
        for (int j = 0; j < 4; j++) {
            int p = p0 + tx * 4 + j;
            if (p < HW) out[p * (NBATCH * 128) + n * 128 + o] = acc[i][j] + bb;
        }
    }
}

// ---------------------------------------------------------------------------
extern "C" void kernel_launch(void* const* d_in, const int* in_sizes, int n_in,
                              void* d_out, int out_size) {
    const float* q     = (const float*)d_in[0];
    const float* v     = (const float*)d_in[2];
    const float* u     = (const float*)d_in[3];
    const float* Wqk   = (const float*)d_in[4];
    const float* bqk   = (const float*)d_in[5];
    const float* Wv    = (const float*)d_in[6];
    const float* bv    = (const float*)d_in[7];
    const float* Wu    = (const float*)d_in[8];
    const float* bu    = (const float*)d_in[9];
    const float* Wrel  = (const float*)d_in[10];
    const float* brel  = (const float*)d_in[11];
    const float* Wdw   = (const float*)d_in[12];
    const float* Wproj = (const float*)d_in[13];
    const float* bproj = (const float*)d_in[14];
    float* out = (float*)d_out;

    const int OUT0 = HW * NBATCH * 128;                 // 230400
    const int OUT1 = NBATCH * NHEAD * WS2 * HW;         // 3240000
    int use_ext = (out_size >= OUT0 + OUT1) ? 1 : 0;

    float* attn_dst;
    if (use_ext) attn_dst = out + OUT0;
    else         cudaGetSymbolAddress((void**)&attn_dst, g_attn_fb);

    const int attn_smem = (2 * 32 * TPIX + 32 * WS2 + WS2 + 30 * WS2) * (int)sizeof(float);
    cudaFuncSetAttribute(k_attn, cudaFuncAttributeMaxDynamicSharedMemorySize, attn_smem);

    k_pre <<<dim3(15, 24),   256>>>(q, v, u, Wqk, bqk, Wv, bv, Wu, bu);
    k_attn<<<dim3(30, 8, 2), 960, attn_smem>>>(attn_dst, Wrel, brel);
    k_dw  <<<dim3(450),      256>>>(Wdw);
    k_proj<<<dim3(15, 4, 2), 256>>>(Wproj, bproj, out);
}